// round 12
// baseline (speedup 1.0000x reference)
#include <cuda_runtime.h>
#include <cuda_bf16.h>
#include <math.h>
#include <cstdint>

#define T_SEQ 128
#define NB 32
#define HD 1024
#define NV 32000
#define NROWS 4096          // T_SEQ * NB

// ------------------- static device scratch (no allocations) -------------------
__device__ __nv_bfloat16 g_xhi [(size_t)NROWS*HD];
__device__ __nv_bfloat16 g_xlo [(size_t)NROWS*HD];
__device__ __nv_bfloat16 g_yshi[(size_t)NROWS*HD];
__device__ __nv_bfloat16 g_yslo[(size_t)NROWS*HD];
__device__ __nv_bfloat16 g_wihhi[(size_t)2*HD*HD];
__device__ __nv_bfloat16 g_wihlo[(size_t)2*HD*HD];
__device__ __nv_bfloat16 g_woutbf[(size_t)NV*HD];
__device__ float g_xW[(size_t)NROWS*HD];
__device__ float g_hbuf[2*HD*NB];
__device__ float g_hfin[2*NB*HD];
__device__ unsigned g_flags[128*8];   // per-block barrier flags, 32B stride

// ------------------- helpers -------------------
__device__ __forceinline__ void cp16ca(void* dst, const void* src){
    unsigned d = (unsigned)__cvta_generic_to_shared(dst);
    asm volatile("cp.async.ca.shared.global [%0], [%1], 16;\n" :: "r"(d), "l"(src));
}
__device__ __forceinline__ void cp16cg(void* dst, const void* src){
    unsigned d = (unsigned)__cvta_generic_to_shared(dst);
    asm volatile("cp.async.cg.shared.global [%0], [%1], 16;\n" :: "r"(d), "l"(src));
}
__device__ __forceinline__ void cp_commit(){ asm volatile("cp.async.commit_group;\n"); }
__device__ __forceinline__ void cp_wait0(){ asm volatile("cp.async.wait_group 0;\n" ::: "memory"); }
__device__ __forceinline__ void cp_wait1(){ asm volatile("cp.async.wait_group 1;\n" ::: "memory"); }

__device__ __forceinline__ void mma16816(float* c, const unsigned* a, const unsigned* b){
    asm volatile(
        "mma.sync.aligned.m16n8k16.row.col.f32.bf16.bf16.f32 "
        "{%0,%1,%2,%3}, {%4,%5,%6,%7}, {%8,%9}, {%0,%1,%2,%3};\n"
        : "+f"(c[0]), "+f"(c[1]), "+f"(c[2]), "+f"(c[3])
        : "r"(a[0]), "r"(a[1]), "r"(a[2]), "r"(a[3]), "r"(b[0]), "r"(b[1]));
}

__device__ __forceinline__ void split2(float x, __nv_bfloat16& h, __nv_bfloat16& l){
    h = __float2bfloat16(x);
    l = __float2bfloat16(x - __bfloat162float(h));
}

// packed fp32x2 FMA (sm_103a FFMA2 — only reachable via PTX)
__device__ __forceinline__ unsigned long long pk2(float x){
    unsigned long long r; unsigned u = __float_as_uint(x);
    asm("mov.b64 %0, {%1, %1};" : "=l"(r) : "r"(u));
    return r;
}
__device__ __forceinline__ void fma2(unsigned long long& d, unsigned long long a, unsigned long long b){
    asm("fma.rn.f32x2 %0, %1, %2, %0;" : "+l"(d) : "l"(a), "l"(b));
}

// ------------------- elementwise kernels -------------------
__global__ void f2bf_kernel(const float* __restrict__ x, __nv_bfloat16* __restrict__ y, int n4){
    int i = blockIdx.x * blockDim.x + threadIdx.x;
    int stride = gridDim.x * blockDim.x;
    for (; i < n4; i += stride){
        float4 v = ((const float4*)x)[i];
        __nv_bfloat162* o = (__nv_bfloat162*)y + (size_t)i*2;
        o[0] = __floats2bfloat162_rn(v.x, v.y);
        o[1] = __floats2bfloat162_rn(v.z, v.w);
    }
}

__global__ void f2bf_split_kernel(const float* __restrict__ x,
        __nv_bfloat16* __restrict__ hi, __nv_bfloat16* __restrict__ lo, int n4){
    int i = blockIdx.x * blockDim.x + threadIdx.x;
    int stride = gridDim.x * blockDim.x;
    for (; i < n4; i += stride){
        float4 v = ((const float4*)x)[i];
        __nv_bfloat16 h0,l0,h1,l1,h2,l2,h3,l3;
        split2(v.x,h0,l0); split2(v.y,h1,l1); split2(v.z,h2,l2); split2(v.w,h3,l3);
        __nv_bfloat162* oh = (__nv_bfloat162*)hi + (size_t)i*2;
        __nv_bfloat162* ol = (__nv_bfloat162*)lo + (size_t)i*2;
        oh[0] = __nv_bfloat162(h0,h1); oh[1] = __nv_bfloat162(h2,h3);
        ol[0] = __nv_bfloat162(l0,l1); ol[1] = __nv_bfloat162(l2,l3);
    }
}

__global__ void embed_split_kernel(const int* __restrict__ tok, const float* __restrict__ emb,
        __nv_bfloat16* __restrict__ hi, __nv_bfloat16* __restrict__ lo){
    int r = blockIdx.x;
    int t = tok[r];
    int e = threadIdx.x * 4;
    float4 v = *(const float4*)(emb + (size_t)t*HD + e);
    __nv_bfloat16 h0,l0,h1,l1,h2,l2,h3,l3;
    split2(v.x,h0,l0); split2(v.y,h1,l1); split2(v.z,h2,l2); split2(v.w,h3,l3);
    __nv_bfloat162* oh = (__nv_bfloat162*)(hi + (size_t)r*HD + e);
    __nv_bfloat162* ol = (__nv_bfloat162*)(lo + (size_t)r*HD + e);
    oh[0] = __nv_bfloat162(h0,h1); oh[1] = __nv_bfloat162(h2,h3);
    ol[0] = __nv_bfloat162(l0,l1); ol[1] = __nv_bfloat162(l2,l3);
}

__global__ void zero_bar_kernel(){ g_flags[threadIdx.x*8] = 0u; }  // 128 threads

__global__ void copy_hidden_kernel(float* __restrict__ dst){
    int i = blockIdx.x * 1024 + threadIdx.x;
    dst[i] = g_hfin[i];
}

// ------------------- big-tile bf16 GEMM: C[M,N] = A[M,K] @ B[N,K]^T + bias ---------
// 128x128x32 tiles, 256 threads (8 warps, 4m x 2n), 2-stage cp.async.
__global__ void __launch_bounds__(256) gemm128(const __nv_bfloat16* __restrict__ A,
        const __nv_bfloat16* __restrict__ B, const float* __restrict__ bias,
        float* __restrict__ C, int M, int N, int K, int mGroup)
{
    __shared__ __align__(16) __nv_bfloat16 As[2][128*40];
    __shared__ __align__(16) __nv_bfloat16 Bs[2][128*40];
    const int nt = N >> 7;
    const int per = nt * mGroup;
    const int grp = blockIdx.x / per;
    const int rem = blockIdx.x % per;
    const int n_t = rem / mGroup;
    const int m_t = grp * mGroup + rem % mGroup;
    const int m0 = m_t << 7, n0 = n_t << 7;

    const int tid = threadIdx.x;
    const int w = tid >> 5, l = tid & 31;
    const int wm = (w & 3) << 5;
    const int wn = (w >> 2) << 6;
    const int g = l >> 2, tg = l & 3;

    float acc[2][8][4];
    #pragma unroll
    for (int i = 0; i < 2; i++)
        #pragma unroll
        for (int j = 0; j < 8; j++)
            #pragma unroll
            for (int q = 0; q < 4; q++) acc[i][j][q] = 0.f;

    auto stage = [&](int s, int k0){
        #pragma unroll
        for (int i = 0; i < 2; i++){
            int c = tid + i*256;
            int row = c >> 2, kc = c & 3;
            cp16ca(&As[s][row*40 + kc*8], A + (size_t)(m0+row)*K + k0 + kc*8);
            cp16ca(&Bs[s][row*40 + kc*8], B + (size_t)(n0+row)*K + k0 + kc*8);
        }
        cp_commit();
    };

    stage(0, 0);
    const int kt = K >> 5;
    cp_wait0(); __syncthreads();

    for (int t = 0; t < kt; t++){
        if (t + 1 < kt) stage((t+1) & 1, (t+1) << 5);
        const __nv_bfloat16* as = As[t & 1];
        const __nv_bfloat16* bs = Bs[t & 1];
        #pragma unroll
        for (int kk = 0; kk < 2; kk++){
            int kc = kk << 4;
            unsigned af[2][4], bfr[8][2];
            #pragma unroll
            for (int mi = 0; mi < 2; mi++){
                int row = wm + (mi<<4) + g;
                af[mi][0] = *(const unsigned*)(as + row*40     + kc + 2*tg);
                af[mi][1] = *(const unsigned*)(as + (row+8)*40 + kc + 2*tg);
                af[mi][2] = *(const unsigned*)(as + row*40     + kc + 2*tg + 8);
                af[mi][3] = *(const unsigned*)(as + (row+8)*40 + kc + 2*tg + 8);
            }
            #pragma unroll
            for (int ni = 0; ni < 8; ni++){
                int row = wn + (ni<<3) + g;
                bfr[ni][0] = *(const unsigned*)(bs + row*40 + kc + 2*tg);
                bfr[ni][1] = *(const unsigned*)(bs + row*40 + kc + 2*tg + 8);
            }
            #pragma unroll
            for (int mi = 0; mi < 2; mi++)
                #pragma unroll
                for (int ni = 0; ni < 8; ni++)
                    mma16816(acc[mi][ni], af[mi], bfr[ni]);
        }
        if (t + 1 < kt){ cp_wait0(); __syncthreads(); }
    }

    #pragma unroll
    for (int mi = 0; mi < 2; mi++){
        int mrow = m0 + wm + (mi<<4) + g;
        #pragma unroll
        for (int ni = 0; ni < 8; ni++){
            int nc = n0 + wn + (ni<<3) + 2*tg;
            float b0 = bias[nc], b1 = bias[nc+1];
            C[(size_t)mrow*N + nc]       = acc[mi][ni][0] + b0;
            C[(size_t)mrow*N + nc + 1]   = acc[mi][ni][1] + b1;
            C[(size_t)(mrow+8)*N + nc]   = acc[mi][ni][2] + b0;
            C[(size_t)(mrow+8)*N + nc+1] = acc[mi][ni][3] + b1;
        }
    }
}

// ------------------- split-precision big-tile GEMM: C = (Ah+Al)(Bh+Bl)^T + bias ----
// 128x128x32 tiles, 256 threads, hi/lo split (3 MMA terms), dynamic smem 80KB.
__global__ void __launch_bounds__(256) gemm128s(
        const __nv_bfloat16* __restrict__ Ah, const __nv_bfloat16* __restrict__ Al,
        const __nv_bfloat16* __restrict__ Bh, const __nv_bfloat16* __restrict__ Bl,
        const float* __restrict__ bias, float* __restrict__ C, int M, int N, int K)
{
    extern __shared__ __align__(16) __nv_bfloat16 dsm[];
    __nv_bfloat16* AhS = dsm;            // [2][128*40]
    __nv_bfloat16* AlS = dsm + 10240;
    __nv_bfloat16* BhS = dsm + 20480;
    __nv_bfloat16* BlS = dsm + 30720;    // total 2x stages laid out per-stage below
    // stage s occupies offset s*5120 within each 10240-elem region

    const int tid = threadIdx.x;
    const int m0 = blockIdx.y << 7, n0 = blockIdx.x << 7;
    const int w = tid >> 5, l = tid & 31;
    const int wm = (w & 3) << 5;
    const int wn = (w >> 2) << 6;
    const int g = l >> 2, tg = l & 3;

    float acc[2][8][4];
    #pragma unroll
    for (int i = 0; i < 2; i++)
        #pragma unroll
        for (int j = 0; j < 8; j++)
            #pragma unroll
            for (int q = 0; q < 4; q++) acc[i][j][q] = 0.f;

    auto stage = [&](int s, int k0){
        // 2048 cp.async tasks: 4 arrays x 512 (128 rows x 4 chunks of 16B)
        #pragma unroll
        for (int i = 0; i < 8; i++){
            int task = tid + i*256;
            int arr = task >> 9, t2 = task & 511;
            int row = t2 >> 2, kc = t2 & 3;
            int so = s*5120 + row*40 + kc*8;
            size_t goff;
            const __nv_bfloat16* gp;
            __nv_bfloat16* sp;
            if (arr == 0){ gp = Ah; goff = (size_t)(m0+row)*K + k0 + kc*8; sp = AhS; }
            else if (arr == 1){ gp = Al; goff = (size_t)(m0+row)*K + k0 + kc*8; sp = AlS; }
            else if (arr == 2){ gp = Bh; goff = (size_t)(n0+row)*K + k0 + kc*8; sp = BhS; }
            else { gp = Bl; goff = (size_t)(n0+row)*K + k0 + kc*8; sp = BlS; }
            cp16ca(sp + so, gp + goff);
        }
        cp_commit();
    };

    stage(0, 0);
    const int kt = K >> 5;
    cp_wait0(); __syncthreads();

    for (int t = 0; t < kt; t++){
        if (t + 1 < kt) stage((t+1) & 1, (t+1) << 5);
        const int so = (t & 1)*5120;
        const __nv_bfloat16* ash = AhS + so;
        const __nv_bfloat16* asl = AlS + so;
        const __nv_bfloat16* bsh = BhS + so;
        const __nv_bfloat16* bsl = BlS + so;
        #pragma unroll
        for (int kk = 0; kk < 2; kk++){
            int kc = kk << 4;
            unsigned afh[2][4], afl[2][4], bfh[8][2], bfl[8][2];
            #pragma unroll
            for (int mi = 0; mi < 2; mi++){
                int row = wm + (mi<<4) + g;
                int o0 = row*40 + kc + 2*tg, o1 = (row+8)*40 + kc + 2*tg;
                afh[mi][0] = *(const unsigned*)(ash + o0);
                afh[mi][1] = *(const unsigned*)(ash + o1);
                afh[mi][2] = *(const unsigned*)(ash + o0 + 8);
                afh[mi][3] = *(const unsigned*)(ash + o1 + 8);
                afl[mi][0] = *(const unsigned*)(asl + o0);
                afl[mi][1] = *(const unsigned*)(asl + o1);
                afl[mi][2] = *(const unsigned*)(asl + o0 + 8);
                afl[mi][3] = *(const unsigned*)(asl + o1 + 8);
            }
            #pragma unroll
            for (int ni = 0; ni < 8; ni++){
                int row = wn + (ni<<3) + g;
                int o = row*40 + kc + 2*tg;
                bfh[ni][0] = *(const unsigned*)(bsh + o);
                bfh[ni][1] = *(const unsigned*)(bsh + o + 8);
                bfl[ni][0] = *(const unsigned*)(bsl + o);
                bfl[ni][1] = *(const unsigned*)(bsl + o + 8);
            }
            #pragma unroll
            for (int mi = 0; mi < 2; mi++)
                #pragma unroll
                for (int ni = 0; ni < 8; ni++){
                    mma16816(acc[mi][ni], afh[mi], bfh[ni]);
                    mma16816(acc[mi][ni], afh[mi], bfl[ni]);
                    mma16816(acc[mi][ni], afl[mi], bfh[ni]);
                }
        }
        if (t + 1 < kt){ cp_wait0(); __syncthreads(); }
    }

    #pragma unroll
    for (int mi = 0; mi < 2; mi++){
        int mrow = m0 + wm + (mi<<4) + g;
        #pragma unroll
        for (int ni = 0; ni < 8; ni++){
            int nc = n0 + wn + (ni<<3) + 2*tg;
            float b0 = bias[nc], b1 = bias[nc+1];
            C[(size_t)mrow*N + nc]       = acc[mi][ni][0] + b0;
            C[(size_t)mrow*N + nc + 1]   = acc[mi][ni][1] + b1;
            C[(size_t)(mrow+8)*N + nc]   = acc[mi][ni][2] + b0;
            C[(size_t)(mrow+8)*N + nc+1] = acc[mi][ni][3] + b1;
        }
    }
}
#define G128S_SMEM (40960 * (int)sizeof(__nv_bfloat16))   // 81920 bytes

// ------------------- recurrence: persistent kernel, flag barrier per step ----------
#define REC_SMEM_FLOATS (32768 + 8224 + 1024 + 8)
#define REC_SMEM_BYTES  (REC_SMEM_FLOATS * 4)

// Distributed-flag barrier: block writes its epoch flag; all 128 threads each
// poll one distinct block's flag. No atomics, no shared-counter contention.
__device__ __forceinline__ void grid_barrier(unsigned epoch){
    __syncthreads();
    if (threadIdx.x == 0){
        __threadfence();
        asm volatile("st.global.relaxed.gpu.u32 [%0], %1;"
                     :: "l"(&g_flags[blockIdx.x*8]), "r"(epoch) : "memory");
    }
    unsigned* f = &g_flags[threadIdx.x*8];
    unsigned v;
    do {
        asm volatile("ld.global.acquire.gpu.u32 %0, [%1];" : "=r"(v) : "l"(f) : "memory");
    } while (v < epoch);
    __syncthreads();
}

__global__ void __launch_bounds__(128, 1) rnn_rec(const float* __restrict__ xW,
        const float* __restrict__ Whh, const float* __restrict__ bhh,
        const float* __restrict__ h0, __nv_bfloat16* __restrict__ ys_hi,
        __nv_bfloat16* __restrict__ ys_lo, float* __restrict__ hfin)
{
    extern __shared__ __align__(16) float sm[];
    float* hT_s  = sm;                 // 32768
    float* Wh_s  = sm + 32768;         // 8*1028
    float* red   = sm + 32768 + 8224;  // 1024
    float* bhh_s = red + 1024;         // 8

    const int tid = threadIdx.x;
    const int w = tid >> 5, l = tid & 31;
    const int rr = l >> 3, bb = l & 7;
    const int hbase = blockIdx.x * 8;
    unsigned bar_t = 0;

    for (int c = tid; c < 2048; c += 128){
        int r = c >> 8, kc = (c & 255) * 4;
        cp16ca(Wh_s + r*1028 + kc, Whh + (size_t)(hbase + r)*HD + kc);
    }
    if (tid < 8) bhh_s[tid] = bhh[hbase + tid];
    for (int i = tid; i < 256; i += 128){
        int r = i >> 5, b = i & 31;
        g_hbuf[(hbase + r)*NB + b] = h0[(size_t)b*HD + hbase + r];
    }
    cp_commit(); cp_wait0();
    bar_t++; grid_barrier(bar_t);

    const int r0 = tid >> 5,         b0 = tid & 31;
    const int r1 = (tid + 128) >> 5, b1 = (tid + 128) & 31;

    for (int t = 0; t < T_SEQ; t++){
        const float* hg = g_hbuf + (size_t)(t & 1) * HD * NB;

        float xw0 = __ldg(xW + (size_t)(t*NB + b0)*HD + hbase + r0);
        float xw1 = __ldg(xW + (size_t)(t*NB + b1)*HD + hbase + r1);

        // stage chunk 0
        #pragma unroll
        for (int i = 0; i < 16; i++){
            int f = tid + i*128;
            cp16cg(hT_s + f*4, hg + f*4);
        }
        cp_commit();

        unsigned long long a0p = 0ull, a0q = 0ull, a1p = 0ull, a1q = 0ull;
        const float* w0p = Wh_s + (2*rr)*1028;
        const float* w1p = w0p + 1028;
        const float* hp  = hT_s + bb*4;

        #pragma unroll
        for (int c = 0; c < 4; c++){
            if (c < 3){
                #pragma unroll
                for (int i = 0; i < 16; i++){
                    int f = (c+1)*2048 + tid + i*128;
                    cp16cg(hT_s + f*4, hg + f*4);
                }
                cp_commit();
                cp_wait1();
            } else {
                cp_wait0();
            }
            __syncthreads();

            const int kb = c*256 + w*64;
            #pragma unroll 4
            for (int gi = 0; gi < 16; gi++){
                int k = kb + gi*4;
                float4 wa = *(const float4*)(w0p + k);
                float4 wb = *(const float4*)(w1p + k);
                ulonglong2 h0v = *(const ulonglong2*)(hp + (size_t)k*32);
                ulonglong2 h1v = *(const ulonglong2*)(hp + (size_t)(k+1)*32);
                ulonglong2 h2v = *(const ulonglong2*)(hp + (size_t)(k+2)*32);
                ulonglong2 h3v = *(const ulonglong2*)(hp + (size_t)(k+3)*32);
                unsigned long long p;
                p = pk2(wa.x); fma2(a0p, p, h0v.x); fma2(a0q, p, h0v.y);
                p = pk2(wb.x); fma2(a1p, p, h0v.x); fma2(a1q, p, h0v.y);
                p = pk2(wa.y); fma2(a0p, p, h1v.x); fma2(a0q, p, h1v.y);
                p = pk2(wb.y); fma2(a1p, p, h1v.x); fma2(a1q, p, h1v.y);
                p = pk2(wa.z); fma2(a0p, p, h2v.x); fma2(a0q, p, h2v.y);
                p = pk2(wb.z); fma2(a1p, p, h2v.x); fma2(a1q, p, h2v.y);
                p = pk2(wa.w); fma2(a0p, p, h3v.x); fma2(a0q, p, h3v.y);
                p = pk2(wb.w); fma2(a1p, p, h3v.x); fma2(a1q, p, h3v.y);
            }
        }

        float2 A0p = *(float2*)&a0p, A0q = *(float2*)&a0q;
        float2 A1p = *(float2*)&a1p, A1q = *(float2*)&a1q;
        float* rw = red + w*256;
        int base = (2*rr)*32 + bb*4;
        rw[base+0]=A0p.x; rw[base+1]=A0p.y; rw[base+2]=A0q.x; rw[base+3]=A0q.y;
        rw[base+32+0]=A1p.x; rw[base+32+1]=A1p.y; rw[base+32+2]=A1q.x; rw[base+32+3]=A1q.y;
        __syncthreads();

        float* hnext = g_hbuf + (size_t)((t+1) & 1) * HD * NB;
        {
            float ssum = red[tid] + red[256+tid] + red[512+tid] + red[768+tid];
            int hg0 = hbase + r0;
            float val = tanhf(ssum + xw0 + bhh_s[r0]);
            hnext[hg0*NB + b0] = val;
            size_t yidx = (size_t)(t*NB + b0)*HD + hg0;
            __nv_bfloat16 vh = __float2bfloat16(val);
            ys_hi[yidx] = vh;
            ys_lo[yidx] = __float2bfloat16(val - __bfloat162float(vh));
            if (t == T_SEQ - 1) hfin[(size_t)b0*HD + hg0] = val;

            int i1 = tid + 128;
            float ssum1 = red[i1] + red[256+i1] + red[512+i1] + red[768+i1];
            int hg1 = hbase + r1;
            float val1 = tanhf(ssum1 + xw1 + bhh_s[r1]);
            hnext[hg1*NB + b1] = val1;
            size_t yidx1 = (size_t)(t*NB + b1)*HD + hg1;
            __nv_bfloat16 vh1 = __float2bfloat16(val1);
            ys_hi[yidx1] = vh1;
            ys_lo[yidx1] = __float2bfloat16(val1 - __bfloat162float(vh1));
            if (t == T_SEQ - 1) hfin[(size_t)b1*HD + hg1] = val1;
        }
        bar_t++; grid_barrier(bar_t);
    }
}

// ------------------- fused log-softmax (LSE + subtract; row stays in L2) -------------------
__global__ void lse_sub_kernel(float* __restrict__ out){
    __shared__ float sm_m[8], sm_s[8];
    __shared__ float s_lse;
    int row = blockIdx.x;
    float4* p = (float4*)(out + (size_t)row*NV);
    float m = -1e30f, s = 0.f;
    for (int i = threadIdx.x; i < NV/4; i += 256){
        float4 v = p[i];
        float lm = fmaxf(fmaxf(v.x, v.y), fmaxf(v.z, v.w));
        float nm = fmaxf(m, lm);
        s = s*__expf(m-nm) + __expf(v.x-nm) + __expf(v.y-nm) + __expf(v.z-nm) + __expf(v.w-nm);
        m = nm;
    }
    #pragma unroll
    for (int o = 16; o > 0; o >>= 1){
        float om = __shfl_xor_sync(0xffffffffu, m, o);
        float os = __shfl_xor_sync(0xffffffffu, s, o);
        float nm = fmaxf(m, om);
        s = s*__expf(m-nm) + os*__expf(om-nm);
        m = nm;
    }
    if ((threadIdx.x & 31) == 0){ sm_m[threadIdx.x>>5] = m; sm_s[threadIdx.x>>5] = s; }
    __syncthreads();
    if (threadIdx.x == 0){
        m = sm_m[0]; s = sm_s[0];
        for (int i = 1; i < 8; i++){
            float om = sm_m[i], os = sm_s[i];
            float nm = fmaxf(m, om);
            s = s*__expf(m-nm) + os*__expf(om-nm);
            m = nm;
        }
        s_lse = m + logf(s);
    }
    __syncthreads();
    float L = s_lse;
    for (int i = threadIdx.x; i < NV/4; i += 256){
        float4 v = p[i];
        v.x -= L; v.y -= L; v.z -= L; v.w -= L;
        p[i] = v;
    }
}

// ------------------- launch -------------------
extern "C" void kernel_launch(void* const* d_in, const int* in_sizes, int n_in,
                              void* d_out, int out_size) {
    const int*   input_x = (const int*)  d_in[0];
    const float* hidden  = (const float*)d_in[1];
    const float* emb     = (const float*)d_in[2];
    const float* W_ih    = (const float*)d_in[3];
    const float* W_hh    = (const float*)d_in[4];
    const float* b_ih    = (const float*)d_in[5];
    const float* b_hh    = (const float*)d_in[6];
    const float* W_out   = (const float*)d_in[7];
    const float* b_out   = (const float*)d_in[8];
    float* out = (float*)d_out;

    void *p_xhi, *p_xlo, *p_yshi, *p_yslo, *p_wihhi, *p_wihlo, *p_woutbf, *p_xW, *p_hfin;
    cudaGetSymbolAddress(&p_xhi,   g_xhi);
    cudaGetSymbolAddress(&p_xlo,   g_xlo);
    cudaGetSymbolAddress(&p_yshi,  g_yshi);
    cudaGetSymbolAddress(&p_yslo,  g_yslo);
    cudaGetSymbolAddress(&p_wihhi, g_wihhi);
    cudaGetSymbolAddress(&p_wihlo, g_wihlo);
    cudaGetSymbolAddress(&p_woutbf, g_woutbf);
    cudaGetSymbolAddress(&p_xW,    g_xW);
    cudaGetSymbolAddress(&p_hfin,  g_hfin);

    cudaFuncSetAttribute(rnn_rec, cudaFuncAttributeMaxDynamicSharedMemorySize, REC_SMEM_BYTES);
    cudaFuncSetAttribute(gemm128s, cudaFuncAttributeMaxDynamicSharedMemorySize, G128S_SMEM);

    __nv_bfloat16* xhi   = (__nv_bfloat16*)p_xhi;
    __nv_bfloat16* xlo   = (__nv_bfloat16*)p_xlo;
    __nv_bfloat16* yshi  = (__nv_bfloat16*)p_yshi;
    __nv_bfloat16* yslo  = (__nv_bfloat16*)p_yslo;
    __nv_bfloat16* wihhi = (__nv_bfloat16*)p_wihhi;
    __nv_bfloat16* wihlo = (__nv_bfloat16*)p_wihlo;
    __nv_bfloat16* woutbf= (__nv_bfloat16*)p_woutbf;
    float* xW   = (float*)p_xW;
    float* hfin = (float*)p_hfin;

    // weight conversions
    f2bf_split_kernel<<<1024, 256>>>(W_ih, wihhi, wihlo, 2*HD*HD/4);
    f2bf_kernel<<<4096, 256>>>(W_out, woutbf, NV*HD/4);
    // embedding gather -> hi/lo bf16
    embed_split_kernel<<<NROWS, 256>>>(input_x, emb, xhi, xlo);

    // layer 0: split-precision input projection, fp32 recurrence
    gemm128s<<<dim3(HD/128, NROWS/128), 256, G128S_SMEM>>>(xhi, xlo, wihhi, wihlo, b_ih, xW, NROWS, HD, HD);
    zero_bar_kernel<<<1, 128>>>();
    rnn_rec<<<128, 128, REC_SMEM_BYTES>>>(xW, W_hh, b_hh, hidden, yshi, yslo, hfin);

    // layer 1
    gemm128s<<<dim3(HD/128, NROWS/128), 256, G128S_SMEM>>>(yshi, yslo, wihhi + (size_t)HD*HD,
            wihlo + (size_t)HD*HD, b_ih + HD, xW, NROWS, HD, HD);
    zero_bar_kernel<<<1, 128>>>();
    rnn_rec<<<128, 128, REC_SMEM_BYTES>>>(xW, W_hh + (size_t)HD*HD, b_hh + HD,
            hidden + (size_t)NB*HD, yshi, yslo, hfin + (size_t)NB*HD);

    // output projection -> logits into d_out (big-tile GEMM, m-group L2 swizzle)
    gemm128<<<(NROWS/128)*(NV/128), 256>>>(yshi, woutbf, b_out, out, NROWS, NV, HD, 8);

    // fused log-softmax in place
    lse_sub_kernel<<<NROWS, 256>>>(out);

    // hidden state tail
    if (out_size >= NROWS*NV + 2*NB*HD)
        copy_hidden_kernel<<<64, 1024>>>(out + (size_t)NROWS*NV);
}

// round 13
// speedup vs baseline: 1.1402x; 1.1402x over previous
#include <cuda_runtime.h>
#include <cuda_bf16.h>
#include <math.h>
#include <cstdint>

#define T_SEQ 128
#define NB 32
#define HD 1024
#define NV 32000
#define NROWS 4096          // T_SEQ * NB

// ------------------- static device scratch (no allocations) -------------------
__device__ __nv_bfloat16 g_xhi [(size_t)NROWS*HD];
__device__ __nv_bfloat16 g_xlo [(size_t)NROWS*HD];
__device__ __nv_bfloat16 g_yshi[(size_t)NROWS*HD];
__device__ __nv_bfloat16 g_yslo[(size_t)NROWS*HD];
__device__ __nv_bfloat16 g_wihhi[(size_t)2*HD*HD];
__device__ __nv_bfloat16 g_wihlo[(size_t)2*HD*HD];
__device__ __nv_bfloat16 g_woutbf[(size_t)NV*HD];
__device__ float g_xW[(size_t)NROWS*HD];
__device__ float g_hbuf[2*HD*NB];
__device__ float g_hfin[2*NB*HD];
__device__ unsigned g_bar;

// ------------------- helpers -------------------
__device__ __forceinline__ void cp16ca(void* dst, const void* src){
    unsigned d = (unsigned)__cvta_generic_to_shared(dst);
    asm volatile("cp.async.ca.shared.global [%0], [%1], 16;\n" :: "r"(d), "l"(src));
}
__device__ __forceinline__ void cp16cg(void* dst, const void* src){
    unsigned d = (unsigned)__cvta_generic_to_shared(dst);
    asm volatile("cp.async.cg.shared.global [%0], [%1], 16;\n" :: "r"(d), "l"(src));
}
__device__ __forceinline__ void cp_commit(){ asm volatile("cp.async.commit_group;\n"); }
__device__ __forceinline__ void cp_wait0(){ asm volatile("cp.async.wait_group 0;\n" ::: "memory"); }
__device__ __forceinline__ void cp_wait1(){ asm volatile("cp.async.wait_group 1;\n" ::: "memory"); }

__device__ __forceinline__ void mma16816(float* c, const unsigned* a, const unsigned* b){
    asm volatile(
        "mma.sync.aligned.m16n8k16.row.col.f32.bf16.bf16.f32 "
        "{%0,%1,%2,%3}, {%4,%5,%6,%7}, {%8,%9}, {%0,%1,%2,%3};\n"
        : "+f"(c[0]), "+f"(c[1]), "+f"(c[2]), "+f"(c[3])
        : "r"(a[0]), "r"(a[1]), "r"(a[2]), "r"(a[3]), "r"(b[0]), "r"(b[1]));
}

__device__ __forceinline__ void split2(float x, __nv_bfloat16& h, __nv_bfloat16& l){
    h = __float2bfloat16(x);
    l = __float2bfloat16(x - __bfloat162float(h));
}

// packed fp32x2 FMA (sm_103a FFMA2 — only reachable via PTX)
__device__ __forceinline__ unsigned long long pk2(float x){
    unsigned long long r; unsigned u = __float_as_uint(x);
    asm("mov.b64 %0, {%1, %1};" : "=l"(r) : "r"(u));
    return r;
}
__device__ __forceinline__ void fma2(unsigned long long& d, unsigned long long a, unsigned long long b){
    asm("fma.rn.f32x2 %0, %1, %2, %0;" : "+l"(d) : "l"(a), "l"(b));
}

// ------------------- elementwise kernels -------------------
__global__ void f2bf_kernel(const float* __restrict__ x, __nv_bfloat16* __restrict__ y, int n4){
    int i = blockIdx.x * blockDim.x + threadIdx.x;
    int stride = gridDim.x * blockDim.x;
    for (; i < n4; i += stride){
        float4 v = ((const float4*)x)[i];
        __nv_bfloat162* o = (__nv_bfloat162*)y + (size_t)i*2;
        o[0] = __floats2bfloat162_rn(v.x, v.y);
        o[1] = __floats2bfloat162_rn(v.z, v.w);
    }
}

__global__ void f2bf_split_kernel(const float* __restrict__ x,
        __nv_bfloat16* __restrict__ hi, __nv_bfloat16* __restrict__ lo, int n4){
    int i = blockIdx.x * blockDim.x + threadIdx.x;
    int stride = gridDim.x * blockDim.x;
    for (; i < n4; i += stride){
        float4 v = ((const float4*)x)[i];
        __nv_bfloat16 h0,l0,h1,l1,h2,l2,h3,l3;
        split2(v.x,h0,l0); split2(v.y,h1,l1); split2(v.z,h2,l2); split2(v.w,h3,l3);
        __nv_bfloat162* oh = (__nv_bfloat162*)hi + (size_t)i*2;
        __nv_bfloat162* ol = (__nv_bfloat162*)lo + (size_t)i*2;
        oh[0] = __nv_bfloat162(h0,h1); oh[1] = __nv_bfloat162(h2,h3);
        ol[0] = __nv_bfloat162(l0,l1); ol[1] = __nv_bfloat162(l2,l3);
    }
}

__global__ void embed_split_kernel(const int* __restrict__ tok, const float* __restrict__ emb,
        __nv_bfloat16* __restrict__ hi, __nv_bfloat16* __restrict__ lo){
    int r = blockIdx.x;
    int t = tok[r];
    int e = threadIdx.x * 4;
    float4 v = *(const float4*)(emb + (size_t)t*HD + e);
    __nv_bfloat16 h0,l0,h1,l1,h2,l2,h3,l3;
    split2(v.x,h0,l0); split2(v.y,h1,l1); split2(v.z,h2,l2); split2(v.w,h3,l3);
    __nv_bfloat162* oh = (__nv_bfloat162*)(hi + (size_t)r*HD + e);
    __nv_bfloat162* ol = (__nv_bfloat162*)(lo + (size_t)r*HD + e);
    oh[0] = __nv_bfloat162(h0,h1); oh[1] = __nv_bfloat162(h2,h3);
    ol[0] = __nv_bfloat162(l0,l1); ol[1] = __nv_bfloat162(l2,l3);
}

__global__ void zero_bar_kernel(){ g_bar = 0u; }

__global__ void copy_hidden_kernel(float* __restrict__ dst){
    int i = blockIdx.x * 1024 + threadIdx.x;
    dst[i] = g_hfin[i];
}

// ------------------- big-tile bf16 GEMM: C[M,N] = A[M,K] @ B[N,K]^T + bias ---------
// 128x128x32 tiles, 256 threads (8 warps, 4m x 2n), 2-stage cp.async.
// __launch_bounds__(256,2): cap regs at 128 for 2 CTAs/SM (hide smem-load latency).
__global__ void __launch_bounds__(256, 2) gemm128(const __nv_bfloat16* __restrict__ A,
        const __nv_bfloat16* __restrict__ B, const float* __restrict__ bias,
        float* __restrict__ C, int M, int N, int K, int mGroup)
{
    __shared__ __align__(16) __nv_bfloat16 As[2][128*40];
    __shared__ __align__(16) __nv_bfloat16 Bs[2][128*40];
    const int nt = N >> 7;
    const int per = nt * mGroup;
    const int grp = blockIdx.x / per;
    const int rem = blockIdx.x % per;
    const int n_t = rem / mGroup;
    const int m_t = grp * mGroup + rem % mGroup;
    const int m0 = m_t << 7, n0 = n_t << 7;

    const int tid = threadIdx.x;
    const int w = tid >> 5, l = tid & 31;
    const int wm = (w & 3) << 5;
    const int wn = (w >> 2) << 6;
    const int g = l >> 2, tg = l & 3;

    float acc[2][8][4];
    #pragma unroll
    for (int i = 0; i < 2; i++)
        #pragma unroll
        for (int j = 0; j < 8; j++)
            #pragma unroll
            for (int q = 0; q < 4; q++) acc[i][j][q] = 0.f;

    auto stage = [&](int s, int k0){
        #pragma unroll
        for (int i = 0; i < 2; i++){
            int c = tid + i*256;
            int row = c >> 2, kc = c & 3;
            cp16ca(&As[s][row*40 + kc*8], A + (size_t)(m0+row)*K + k0 + kc*8);
            cp16ca(&Bs[s][row*40 + kc*8], B + (size_t)(n0+row)*K + k0 + kc*8);
        }
        cp_commit();
    };

    stage(0, 0);
    const int kt = K >> 5;
    cp_wait0(); __syncthreads();

    for (int t = 0; t < kt; t++){
        if (t + 1 < kt) stage((t+1) & 1, (t+1) << 5);
        const __nv_bfloat16* as = As[t & 1];
        const __nv_bfloat16* bs = Bs[t & 1];
        #pragma unroll
        for (int kk = 0; kk < 2; kk++){
            int kc = kk << 4;
            unsigned af[2][4], bfr[8][2];
            #pragma unroll
            for (int mi = 0; mi < 2; mi++){
                int row = wm + (mi<<4) + g;
                af[mi][0] = *(const unsigned*)(as + row*40     + kc + 2*tg);
                af[mi][1] = *(const unsigned*)(as + (row+8)*40 + kc + 2*tg);
                af[mi][2] = *(const unsigned*)(as + row*40     + kc + 2*tg + 8);
                af[mi][3] = *(const unsigned*)(as + (row+8)*40 + kc + 2*tg + 8);
            }
            #pragma unroll
            for (int ni = 0; ni < 8; ni++){
                int row = wn + (ni<<3) + g;
                bfr[ni][0] = *(const unsigned*)(bs + row*40 + kc + 2*tg);
                bfr[ni][1] = *(const unsigned*)(bs + row*40 + kc + 2*tg + 8);
            }
            #pragma unroll
            for (int mi = 0; mi < 2; mi++)
                #pragma unroll
                for (int ni = 0; ni < 8; ni++)
                    mma16816(acc[mi][ni], af[mi], bfr[ni]);
        }
        if (t + 1 < kt){ cp_wait0(); __syncthreads(); }
    }

    #pragma unroll
    for (int mi = 0; mi < 2; mi++){
        int mrow = m0 + wm + (mi<<4) + g;
        #pragma unroll
        for (int ni = 0; ni < 8; ni++){
            int nc = n0 + wn + (ni<<3) + 2*tg;
            float b0 = bias[nc], b1 = bias[nc+1];
            C[(size_t)mrow*N + nc]       = acc[mi][ni][0] + b0;
            C[(size_t)mrow*N + nc + 1]   = acc[mi][ni][1] + b1;
            C[(size_t)(mrow+8)*N + nc]   = acc[mi][ni][2] + b0;
            C[(size_t)(mrow+8)*N + nc+1] = acc[mi][ni][3] + b1;
        }
    }
}

// ------------------- split-precision big-tile GEMM: C = (Ah+Al)(Bh+Bl)^T + bias ----
// 128x128x32 tiles, 256 threads, hi/lo split (3 MMA terms), dynamic smem 80KB.
__global__ void __launch_bounds__(256) gemm128s(
        const __nv_bfloat16* __restrict__ Ah, const __nv_bfloat16* __restrict__ Al,
        const __nv_bfloat16* __restrict__ Bh, const __nv_bfloat16* __restrict__ Bl,
        const float* __restrict__ bias, float* __restrict__ C, int M, int N, int K)
{
    extern __shared__ __align__(16) __nv_bfloat16 dsm[];
    __nv_bfloat16* AhS = dsm;            // [2][128*40]
    __nv_bfloat16* AlS = dsm + 10240;
    __nv_bfloat16* BhS = dsm + 20480;
    __nv_bfloat16* BlS = dsm + 30720;

    const int tid = threadIdx.x;
    const int m0 = blockIdx.y << 7, n0 = blockIdx.x << 7;
    const int w = tid >> 5, l = tid & 31;
    const int wm = (w & 3) << 5;
    const int wn = (w >> 2) << 6;
    const int g = l >> 2, tg = l & 3;

    float acc[2][8][4];
    #pragma unroll
    for (int i = 0; i < 2; i++)
        #pragma unroll
        for (int j = 0; j < 8; j++)
            #pragma unroll
            for (int q = 0; q < 4; q++) acc[i][j][q] = 0.f;

    auto stage = [&](int s, int k0){
        #pragma unroll
        for (int i = 0; i < 8; i++){
            int task = tid + i*256;
            int arr = task >> 9, t2 = task & 511;
            int row = t2 >> 2, kc = t2 & 3;
            int so = s*5120 + row*40 + kc*8;
            size_t goff;
            const __nv_bfloat16* gp;
            __nv_bfloat16* sp;
            if (arr == 0){ gp = Ah; goff = (size_t)(m0+row)*K + k0 + kc*8; sp = AhS; }
            else if (arr == 1){ gp = Al; goff = (size_t)(m0+row)*K + k0 + kc*8; sp = AlS; }
            else if (arr == 2){ gp = Bh; goff = (size_t)(n0+row)*K + k0 + kc*8; sp = BhS; }
            else { gp = Bl; goff = (size_t)(n0+row)*K + k0 + kc*8; sp = BlS; }
            cp16ca(sp + so, gp + goff);
        }
        cp_commit();
    };

    stage(0, 0);
    const int kt = K >> 5;
    cp_wait0(); __syncthreads();

    for (int t = 0; t < kt; t++){
        if (t + 1 < kt) stage((t+1) & 1, (t+1) << 5);
        const int so = (t & 1)*5120;
        const __nv_bfloat16* ash = AhS + so;
        const __nv_bfloat16* asl = AlS + so;
        const __nv_bfloat16* bsh = BhS + so;
        const __nv_bfloat16* bsl = BlS + so;
        #pragma unroll
        for (int kk = 0; kk < 2; kk++){
            int kc = kk << 4;
            unsigned afh[2][4], afl[2][4], bfh[8][2], bfl[8][2];
            #pragma unroll
            for (int mi = 0; mi < 2; mi++){
                int row = wm + (mi<<4) + g;
                int o0 = row*40 + kc + 2*tg, o1 = (row+8)*40 + kc + 2*tg;
                afh[mi][0] = *(const unsigned*)(ash + o0);
                afh[mi][1] = *(const unsigned*)(ash + o1);
                afh[mi][2] = *(const unsigned*)(ash + o0 + 8);
                afh[mi][3] = *(const unsigned*)(ash + o1 + 8);
                afl[mi][0] = *(const unsigned*)(asl + o0);
                afl[mi][1] = *(const unsigned*)(asl + o1);
                afl[mi][2] = *(const unsigned*)(asl + o0 + 8);
                afl[mi][3] = *(const unsigned*)(asl + o1 + 8);
            }
            #pragma unroll
            for (int ni = 0; ni < 8; ni++){
                int row = wn + (ni<<3) + g;
                int o = row*40 + kc + 2*tg;
                bfh[ni][0] = *(const unsigned*)(bsh + o);
                bfh[ni][1] = *(const unsigned*)(bsh + o + 8);
                bfl[ni][0] = *(const unsigned*)(bsl + o);
                bfl[ni][1] = *(const unsigned*)(bsl + o + 8);
            }
            #pragma unroll
            for (int mi = 0; mi < 2; mi++)
                #pragma unroll
                for (int ni = 0; ni < 8; ni++){
                    mma16816(acc[mi][ni], afh[mi], bfh[ni]);
                    mma16816(acc[mi][ni], afh[mi], bfl[ni]);
                    mma16816(acc[mi][ni], afl[mi], bfh[ni]);
                }
        }
        if (t + 1 < kt){ cp_wait0(); __syncthreads(); }
    }

    #pragma unroll
    for (int mi = 0; mi < 2; mi++){
        int mrow = m0 + wm + (mi<<4) + g;
        #pragma unroll
        for (int ni = 0; ni < 8; ni++){
            int nc = n0 + wn + (ni<<3) + 2*tg;
            float b0 = bias[nc], b1 = bias[nc+1];
            C[(size_t)mrow*N + nc]       = acc[mi][ni][0] + b0;
            C[(size_t)mrow*N + nc + 1]   = acc[mi][ni][1] + b1;
            C[(size_t)(mrow+8)*N + nc]   = acc[mi][ni][2] + b0;
            C[(size_t)(mrow+8)*N + nc+1] = acc[mi][ni][3] + b1;
        }
    }
}
#define G128S_SMEM (40960 * (int)sizeof(__nv_bfloat16))   // 81920 bytes

// ------------------- recurrence: persistent kernel, atomic-counter barrier ----------
#define REC_SMEM_FLOATS (32768 + 8224 + 1024 + 8)
#define REC_SMEM_BYTES  (REC_SMEM_FLOATS * 4)

__device__ __forceinline__ void grid_barrier(unsigned* bar_t){
    __syncthreads();
    *bar_t += 1;
    if (threadIdx.x == 0){
        __threadfence();
        atomicAdd(&g_bar, 1u);
        unsigned target = (*bar_t) * 128u;
        while (*((volatile unsigned*)&g_bar) < target) { }
        __threadfence();
    }
    __syncthreads();
}

__global__ void __launch_bounds__(128, 1) rnn_rec(const float* __restrict__ xW,
        const float* __restrict__ Whh, const float* __restrict__ bhh,
        const float* __restrict__ h0, __nv_bfloat16* __restrict__ ys_hi,
        __nv_bfloat16* __restrict__ ys_lo, float* __restrict__ hfin)
{
    extern __shared__ __align__(16) float sm[];
    float* hT_s  = sm;                 // 32768
    float* Wh_s  = sm + 32768;         // 8*1028
    float* red   = sm + 32768 + 8224;  // 1024
    float* bhh_s = red + 1024;         // 8

    const int tid = threadIdx.x;
    const int w = tid >> 5, l = tid & 31;
    const int rr = l >> 3, bb = l & 7;
    const int hbase = blockIdx.x * 8;
    unsigned bar_t = 0;

    for (int c = tid; c < 2048; c += 128){
        int r = c >> 8, kc = (c & 255) * 4;
        cp16ca(Wh_s + r*1028 + kc, Whh + (size_t)(hbase + r)*HD + kc);
    }
    if (tid < 8) bhh_s[tid] = bhh[hbase + tid];
    for (int i = tid; i < 256; i += 128){
        int r = i >> 5, b = i & 31;
        g_hbuf[(hbase + r)*NB + b] = h0[(size_t)b*HD + hbase + r];
    }
    cp_commit(); cp_wait0();
    grid_barrier(&bar_t);

    const int r0 = tid >> 5,         b0 = tid & 31;
    const int r1 = (tid + 128) >> 5, b1 = (tid + 128) & 31;

    for (int t = 0; t < T_SEQ; t++){
        const float* hg = g_hbuf + (size_t)(t & 1) * HD * NB;

        float xw0 = __ldg(xW + (size_t)(t*NB + b0)*HD + hbase + r0);
        float xw1 = __ldg(xW + (size_t)(t*NB + b1)*HD + hbase + r1);

        // stage chunk 0
        #pragma unroll
        for (int i = 0; i < 16; i++){
            int f = tid + i*128;
            cp16cg(hT_s + f*4, hg + f*4);
        }
        cp_commit();

        unsigned long long a0p = 0ull, a0q = 0ull, a1p = 0ull, a1q = 0ull;
        const float* w0p = Wh_s + (2*rr)*1028;
        const float* w1p = w0p + 1028;
        const float* hp  = hT_s + bb*4;

        #pragma unroll
        for (int c = 0; c < 4; c++){
            if (c < 3){
                #pragma unroll
                for (int i = 0; i < 16; i++){
                    int f = (c+1)*2048 + tid + i*128;
                    cp16cg(hT_s + f*4, hg + f*4);
                }
                cp_commit();
                cp_wait1();
            } else {
                cp_wait0();
            }
            __syncthreads();

            const int kb = c*256 + w*64;
            #pragma unroll 4
            for (int gi = 0; gi < 16; gi++){
                int k = kb + gi*4;
                float4 wa = *(const float4*)(w0p + k);
                float4 wb = *(const float4*)(w1p + k);
                ulonglong2 h0v = *(const ulonglong2*)(hp + (size_t)k*32);
                ulonglong2 h1v = *(const ulonglong2*)(hp + (size_t)(k+1)*32);
                ulonglong2 h2v = *(const ulonglong2*)(hp + (size_t)(k+2)*32);
                ulonglong2 h3v = *(const ulonglong2*)(hp + (size_t)(k+3)*32);
                unsigned long long p;
                p = pk2(wa.x); fma2(a0p, p, h0v.x); fma2(a0q, p, h0v.y);
                p = pk2(wb.x); fma2(a1p, p, h0v.x); fma2(a1q, p, h0v.y);
                p = pk2(wa.y); fma2(a0p, p, h1v.x); fma2(a0q, p, h1v.y);
                p = pk2(wb.y); fma2(a1p, p, h1v.x); fma2(a1q, p, h1v.y);
                p = pk2(wa.z); fma2(a0p, p, h2v.x); fma2(a0q, p, h2v.y);
                p = pk2(wb.z); fma2(a1p, p, h2v.x); fma2(a1q, p, h2v.y);
                p = pk2(wa.w); fma2(a0p, p, h3v.x); fma2(a0q, p, h3v.y);
                p = pk2(wb.w); fma2(a1p, p, h3v.x); fma2(a1q, p, h3v.y);
            }
        }

        float2 A0p = *(float2*)&a0p, A0q = *(float2*)&a0q;
        float2 A1p = *(float2*)&a1p, A1q = *(float2*)&a1q;
        float* rw = red + w*256;
        int base = (2*rr)*32 + bb*4;
        rw[base+0]=A0p.x; rw[base+1]=A0p.y; rw[base+2]=A0q.x; rw[base+3]=A0q.y;
        rw[base+32+0]=A1p.x; rw[base+32+1]=A1p.y; rw[base+32+2]=A1q.x; rw[base+32+3]=A1q.y;
        __syncthreads();

        float* hnext = g_hbuf + (size_t)((t+1) & 1) * HD * NB;
        {
            float ssum = red[tid] + red[256+tid] + red[512+tid] + red[768+tid];
            int hg0 = hbase + r0;
            float val = tanhf(ssum + xw0 + bhh_s[r0]);
            hnext[hg0*NB + b0] = val;
            size_t yidx = (size_t)(t*NB + b0)*HD + hg0;
            __nv_bfloat16 vh = __float2bfloat16(val);
            ys_hi[yidx] = vh;
            ys_lo[yidx] = __float2bfloat16(val - __bfloat162float(vh));
            if (t == T_SEQ - 1) hfin[(size_t)b0*HD + hg0] = val;

            int i1 = tid + 128;
            float ssum1 = red[i1] + red[256+i1] + red[512+i1] + red[768+i1];
            int hg1 = hbase + r1;
            float val1 = tanhf(ssum1 + xw1 + bhh_s[r1]);
            hnext[hg1*NB + b1] = val1;
            size_t yidx1 = (size_t)(t*NB + b1)*HD + hg1;
            __nv_bfloat16 vh1 = __float2bfloat16(val1);
            ys_hi[yidx1] = vh1;
            ys_lo[yidx1] = __float2bfloat16(val1 - __bfloat162float(vh1));
            if (t == T_SEQ - 1) hfin[(size_t)b1*HD + hg1] = val1;
        }
        grid_barrier(&bar_t);
    }
}

// ------------------- fused log-softmax (LSE + subtract; row stays in L2) -------------------
__global__ void lse_sub_kernel(float* __restrict__ out){
    __shared__ float sm_m[8], sm_s[8];
    __shared__ float s_lse;
    int row = blockIdx.x;
    float4* p = (float4*)(out + (size_t)row*NV);
    float m = -1e30f, s = 0.f;
    for (int i = threadIdx.x; i < NV/4; i += 256){
        float4 v = p[i];
        float lm = fmaxf(fmaxf(v.x, v.y), fmaxf(v.z, v.w));
        float nm = fmaxf(m, lm);
        s = s*__expf(m-nm) + __expf(v.x-nm) + __expf(v.y-nm) + __expf(v.z-nm) + __expf(v.w-nm);
        m = nm;
    }
    #pragma unroll
    for (int o = 16; o > 0; o >>= 1){
        float om = __shfl_xor_sync(0xffffffffu, m, o);
        float os = __shfl_xor_sync(0xffffffffu, s, o);
        float nm = fmaxf(m, om);
        s = s*__expf(m-nm) + os*__expf(om-nm);
        m = nm;
    }
    if ((threadIdx.x & 31) == 0){ sm_m[threadIdx.x>>5] = m; sm_s[threadIdx.x>>5] = s; }
    __syncthreads();
    if (threadIdx.x == 0){
        m = sm_m[0]; s = sm_s[0];
        for (int i = 1; i < 8; i++){
            float om = sm_m[i], os = sm_s[i];
            float nm = fmaxf(m, om);
            s = s*__expf(m-nm) + os*__expf(om-nm);
            m = nm;
        }
        s_lse = m + logf(s);
    }
    __syncthreads();
    float L = s_lse;
    for (int i = threadIdx.x; i < NV/4; i += 256){
        float4 v = p[i];
        v.x -= L; v.y -= L; v.z -= L; v.w -= L;
        p[i] = v;
    }
}

// ------------------- launch -------------------
extern "C" void kernel_launch(void* const* d_in, const int* in_sizes, int n_in,
                              void* d_out, int out_size) {
    const int*   input_x = (const int*)  d_in[0];
    const float* hidden  = (const float*)d_in[1];
    const float* emb     = (const float*)d_in[2];
    const float* W_ih    = (const float*)d_in[3];
    const float* W_hh    = (const float*)d_in[4];
    const float* b_ih    = (const float*)d_in[5];
    const float* b_hh    = (const float*)d_in[6];
    const float* W_out   = (const float*)d_in[7];
    const float* b_out   = (const float*)d_in[8];
    float* out = (float*)d_out;

    void *p_xhi, *p_xlo, *p_yshi, *p_yslo, *p_wihhi, *p_wihlo, *p_woutbf, *p_xW, *p_hfin;
    cudaGetSymbolAddress(&p_xhi,   g_xhi);
    cudaGetSymbolAddress(&p_xlo,   g_xlo);
    cudaGetSymbolAddress(&p_yshi,  g_yshi);
    cudaGetSymbolAddress(&p_yslo,  g_yslo);
    cudaGetSymbolAddress(&p_wihhi, g_wihhi);
    cudaGetSymbolAddress(&p_wihlo, g_wihlo);
    cudaGetSymbolAddress(&p_woutbf, g_woutbf);
    cudaGetSymbolAddress(&p_xW,    g_xW);
    cudaGetSymbolAddress(&p_hfin,  g_hfin);

    cudaFuncSetAttribute(rnn_rec, cudaFuncAttributeMaxDynamicSharedMemorySize, REC_SMEM_BYTES);
    cudaFuncSetAttribute(gemm128s, cudaFuncAttributeMaxDynamicSharedMemorySize, G128S_SMEM);

    __nv_bfloat16* xhi   = (__nv_bfloat16*)p_xhi;
    __nv_bfloat16* xlo   = (__nv_bfloat16*)p_xlo;
    __nv_bfloat16* yshi  = (__nv_bfloat16*)p_yshi;
    __nv_bfloat16* yslo  = (__nv_bfloat16*)p_yslo;
    __nv_bfloat16* wihhi = (__nv_bfloat16*)p_wihhi;
    __nv_bfloat16* wihlo = (__nv_bfloat16*)p_wihlo;
    __nv_bfloat16* woutbf= (__nv_bfloat16*)p_woutbf;
    float* xW   = (float*)p_xW;
    float* hfin = (float*)p_hfin;

    // weight conversions
    f2bf_split_kernel<<<1024, 256>>>(W_ih, wihhi, wihlo, 2*HD*HD/4);
    f2bf_kernel<<<4096, 256>>>(W_out, woutbf, NV*HD/4);
    // embedding gather -> hi/lo bf16
    embed_split_kernel<<<NROWS, 256>>>(input_x, emb, xhi, xlo);

    // layer 0: split-precision input projection, fp32 recurrence
    gemm128s<<<dim3(HD/128, NROWS/128), 256, G128S_SMEM>>>(xhi, xlo, wihhi, wihlo, b_ih, xW, NROWS, HD, HD);
    zero_bar_kernel<<<1, 1>>>();
    rnn_rec<<<128, 128, REC_SMEM_BYTES>>>(xW, W_hh, b_hh, hidden, yshi, yslo, hfin);

    // layer 1
    gemm128s<<<dim3(HD/128, NROWS/128), 256, G128S_SMEM>>>(yshi, yslo, wihhi + (size_t)HD*HD,
            wihlo + (size_t)HD*HD, b_ih + HD, xW, NROWS, HD, HD);
    zero_bar_kernel<<<1, 1>>>();
    rnn_rec<<<128, 128, REC_SMEM_BYTES>>>(xW, W_hh + (size_t)HD*HD, b_hh + HD,
            hidden + (size_t)NB*HD, yshi, yslo, hfin + (size_t)NB*HD);

    // output projection -> logits into d_out (big-tile GEMM, m-group L2 swizzle)
    gemm128<<<(NROWS/128)*(NV/128), 256>>>(yshi, woutbf, b_out, out, NROWS, NV, HD, 8);

    // fused log-softmax in place
    lse_sub_kernel<<<NROWS, 256>>>(out);

    // hidden state tail
    if (out_size >= NROWS*NV + 2*NB*HD)
        copy_hidden_kernel<<<64, 1024>>>(out + (size_t)NROWS*NV);
}